// round 10
// baseline (speedup 1.0000x reference)
#include <cuda_runtime.h>
#include <cuda_bf16.h>

// Problem constants
#define BB 4
#define CC 256
#define HH 256
#define WW 256
#define RR 64
#define HL 64
#define WL 64
#define PL (HL*WL)          // 4096 low-res pixels

typedef unsigned long long u64;

// Scratch (no cudaMalloc allowed -> __device__ globals)
// Partial projections: [which][chalf][b*RR*PL]
__device__ float g_part[2][2][BB*RR*PL];   // 16 MB
__device__ float g_a  [BB*RR*PL];          // 4 MB
__device__ float g_b  [BB*RR*PL];          // 4 MB
__device__ float g_Ai [BB*CC*PL];          // 16 MB  a expanded to C channels (low res)
__device__ float g_Bi [BB*CC*PL];          // 16 MB  b expanded to C channels (low res)

// ---------- packed f32x2 helpers ----------
__device__ __forceinline__ u64 pk2(float lo, float hi) {
    u64 r;
    asm("mov.b64 %0, {%1, %2};" : "=l"(r) : "f"(lo), "f"(hi));
    return r;
}
__device__ __forceinline__ void fma2(u64& acc, u64 a, u64 b) {
    asm("fma.rn.f32x2 %0, %1, %2, %0;" : "+l"(acc) : "l"(a), "l"(b));
}
__device__ __forceinline__ float unpk_sum(u64 v) {
    float lo, hi;
    asm("mov.b64 {%0, %1}, %2;" : "=f"(lo), "=f"(hi) : "l"(v));
    return lo + hi;
}

// ---------- K12: fused 4x downsample + 1x1 projection ----------
// Downsample (align_corners=False, 256->64): lr(i,j) = 0.25 * sum of full-res
// rows {4i+1,4i+2} x cols {4j+1,4j+2}. Then out[b,r,p] = sum_c w[r,c]*lr[b,c,p].
//
// Block = (b, rp: 2 low-res rows = 128 px, z: bit0 = c-half, bit1 = which).
// 8 chunks of 16 channels: phase A downsample -> SMEM, phase B dense FMA.
// launch_bounds(256,3): 24 warps/SM to hide DRAM latency between barriers.
__global__ __launch_bounds__(256, 3) void k_downproj(const float* __restrict__ E,
                                                     const float* __restrict__ D,
                                                     const float* __restrict__ wg,
                                                     const float* __restrict__ wt) {
    __shared__ u64   ws[64 * 64];      // [cpair][r] duplicated-pair weights, 32 KB
    __shared__ float sds[8 * 256];     // [k][px*2+parity], 8 KB

    int b  = blockIdx.x;               // 0..3
    int rp = blockIdx.y;               // 0..31
    int ch    = blockIdx.z & 1;        // c-half
    int which = blockIdx.z >> 1;       // 0: E/w_rg, 1: D/w_rt
    int tid = threadIdx.x;

    const float* X = which ? D : E;
    const float* w = which ? wt : wg;

    // ws[cp*64 + r] = (w[r][c], w[r][c+1]), c = ch*128 + 2*cp
    for (int i = tid; i < 64 * 64; i += 256) {
        int cp = i >> 6, r = i & 63;
        int c = ch * 128 + cp * 2;
        ws[i] = pk2(w[r * CC + c], w[r * CC + c + 1]);
    }
    __syncthreads();

    int px = tid & 127;                // phase-A pixel
    int c_local = tid >> 7;            // c parity within pair
    int j  = px & 63;
    int il = px >> 6;
    int i_lr = rp * 2 + il;

    int warp = tid >> 5, lane = tid & 31;
    int rbase = (warp >> 2) * 32;
    int mypx  = (warp & 3) * 32 + lane;   // 0..127

    u64 acc[32];
    #pragma unroll
    for (int r = 0; r < 32; r++) acc[r] = 0ull;

    const float4* X4 = (const float4*)X;
    size_t f4row = ((size_t)(b * CC) * HH + (4 * i_lr + 1)) * (WW / 4) + j;
    const size_t cstride = (size_t)HH * (WW / 4);   // f4 elems per channel

    for (int chunk = 0; chunk < 8; chunk++) {
        // ---- phase A: downsample 16 channels for 128 px ----
        #pragma unroll 2
        for (int k = 0; k < 8; k++) {
            int c = ch * 128 + chunk * 16 + k * 2 + c_local;
            size_t f0 = f4row + (size_t)c * cstride;
            float4 e0 = X4[f0];
            float4 e1 = X4[f0 + WW / 4];
            sds[k * 256 + px * 2 + c_local] =
                0.25f * (e0.y + e0.z + e1.y + e1.z);
        }
        __syncthreads();

        // ---- phase B: 8 c-pairs of FMA ----
        #pragma unroll
        for (int k = 0; k < 8; k++) {
            u64 dsp = *(const u64*)(sds + k * 256 + mypx * 2);
            const u64* wptr = ws + (chunk * 8 + k) * 64 + rbase;
            #pragma unroll
            for (int rr = 0; rr < 32; rr += 2) {
                ulonglong2 wv = *(const ulonglong2*)(wptr + rr);
                fma2(acc[rr],     dsp, wv.x);
                fma2(acc[rr + 1], dsp, wv.y);
            }
        }
        __syncthreads();
    }

    float* outp = g_part[which][ch] + ((size_t)b * RR + rbase) * PL + rp * 128 + mypx;
    #pragma unroll
    for (int r = 0; r < 32; r++)
        outp[(size_t)r * PL] = unpk_sum(acc[r]);
}

// ---------- K3: 3x3 zero-padded box stats + guided-filter coefficients ----------
#define PITCH 66
__global__ __launch_bounds__(256) void k_guided(const float* __restrict__ epsPtr) {
    __shared__ float sg[PITCH*PITCH];
    __shared__ float st[PITCH*PITCH];
    int br = blockIdx.x;                       // b*RR + r, 256 blocks
    int tid = threadIdx.x;
    const float* g0 = g_part[0][0] + (size_t)br * PL;
    const float* g1 = g_part[0][1] + (size_t)br * PL;
    const float* t0 = g_part[1][0] + (size_t)br * PL;
    const float* t1 = g_part[1][1] + (size_t)br * PL;
    for (int i = tid; i < PITCH*PITCH; i += 256) { sg[i] = 0.0f; st[i] = 0.0f; }
    __syncthreads();
    for (int p = tid; p < PL; p += 256) {
        int i = p >> 6, j = p & 63;
        sg[(i+1)*PITCH + (j+1)] = g0[p] + g1[p];
        st[(i+1)*PITCH + (j+1)] = t0[p] + t1[p];
    }
    __syncthreads();
    float eps = *epsPtr;
    const float inv9 = 1.0f / 9.0f;
    for (int p = tid; p < PL; p += 256) {
        int i = p >> 6, j = p & 63;
        int c = (i+1)*PITCH + (j+1);
        float sgs = 0.f, sts = 0.f, sggs = 0.f, sgts = 0.f;
        #pragma unroll
        for (int di = -1; di <= 1; di++) {
            #pragma unroll
            for (int dj = -1; dj <= 1; dj++) {
                float g = sg[c + di*PITCH + dj];
                float t = st[c + di*PITCH + dj];
                sgs += g; sts += t; sggs += g*g; sgts += g*t;
            }
        }
        float mg  = sgs * inv9;
        float mt  = sts * inv9;
        float var = sggs * inv9 - mg * mg;
        float cov = sgts * inv9 - mg * mt;
        float a   = cov / (var + eps);
        float bb  = mt - a * mg;
        g_a[(size_t)br * PL + p] = a;
        g_b[(size_t)br * PL + p] = bb;
    }
}

// ---------- K4: expand: out[b,o,p] = sum_r w[o,r] * in[b,r,p]  (w: [C, R]) ----------
// Register-tiled (round-4 measured-best variant): 16 o-outputs x 2 pixels/thread.
// blockIdx.z (32): bits[0:4) = o-group (16), bit4 = which tensor.
__global__ __launch_bounds__(128, 5) void k_expand(const float* __restrict__ wa,
                                                   const float* __restrict__ wb) {
    __shared__ float ws[16 * RR];
    int which = blockIdx.z >> 4;
    int og    = blockIdx.z & 15;
    const float* in = which ? g_b  : g_a;
    float* out      = which ? g_Bi : g_Ai;
    const float* w  = which ? wb   : wa;
    int b  = blockIdx.x;          // 0..3
    int pt = blockIdx.y;          // 0..15
    int tid = threadIdx.x;

    const float4* wsrc = (const float4*)(w + og * 16 * RR);
    #pragma unroll
    for (int i = tid; i < 16 * RR / 4; i += 128) ((float4*)ws)[i] = wsrc[i];
    __syncthreads();

    int p0 = pt * 256 + tid;
    const float* inb = in + (size_t)b * RR * PL + p0;

    u64 acc0[16], acc1[16];
    #pragma unroll
    for (int o = 0; o < 16; o++) { acc0[o] = 0ull; acc1[o] = 0ull; }

    #pragma unroll 4
    for (int r = 0; r < RR; r += 4) {
        const float* ip = inb + (size_t)r * PL;
        float a0 = ip[0],      a1 = ip[PL],      a2 = ip[2*PL],      a3 = ip[3*PL];
        float b0 = ip[128],    b1 = ip[PL+128],  b2 = ip[2*PL+128],  b3 = ip[3*PL+128];
        u64 ea0 = pk2(a0, a1), ea1 = pk2(a2, a3);
        u64 eb0 = pk2(b0, b1), eb1 = pk2(b2, b3);
        #pragma unroll
        for (int o = 0; o < 16; o++) {
            const ulonglong2 wv = *(const ulonglong2*)(ws + o * RR + r);
            fma2(acc0[o], ea0, wv.x);
            fma2(acc0[o], ea1, wv.y);
            fma2(acc1[o], eb0, wv.x);
            fma2(acc1[o], eb1, wv.y);
        }
    }
    float* outp = out + ((size_t)b * CC + og * 16) * PL + p0;
    #pragma unroll
    for (int o = 0; o < 16; o++) {
        outp[(size_t)o * PL]       = unpk_sum(acc0[o]);
        outp[(size_t)o * PL + 128] = unpk_sum(acc1[o]);
    }
}

// ---------- K5: fused 4x bilinear upsample + output combine (SMEM-staged) ----------
__global__ __launch_bounds__(256) void k_final(const float* __restrict__ E,
                                               const float* __restrict__ D,
                                               float* __restrict__ out) {
    __shared__ float rawA[6][64], rawB[6][64];
    __shared__ float Ay[16][64], By[16][64];
    int bc = blockIdx.x;      // 0..1023
    int t  = blockIdx.y;      // 0..15 (y tiles of 16)
    int tid = threadIdx.x;
    int base = 4*t - 1;

    const float* Ab = g_Ai + (size_t)bc * PL;
    const float* Bb = g_Bi + (size_t)bc * PL;
    for (int i = tid; i < 6*64; i += 256) {
        int s = i >> 6, c = i & 63;
        int row = min(max(base + s, 0), 63);
        rawA[s][c] = Ab[row*64 + c];
        rawB[s][c] = Bb[row*64 + c];
    }
    __syncthreads();

    for (int i = tid; i < 16*64; i += 256) {
        int yl = i >> 6, c = i & 63;
        int y = t*16 + yl;
        float sy = fmaxf((y + 0.5f) * 0.25f - 0.5f, 0.0f);
        int y0 = (int)sy; if (y0 > 63) y0 = 63;
        int y1 = min(y0 + 1, 63);
        float wy = sy - (float)y0;
        int s0 = y0 - base, s1 = y1 - base;
        float a0 = rawA[s0][c], a1 = rawA[s1][c];
        float b0 = rawB[s0][c], b1 = rawB[s1][c];
        Ay[yl][c] = a0 + wy * (a1 - a0);
        By[yl][c] = b0 + wy * (b1 - b0);
    }
    __syncthreads();

    int yl = tid >> 4;        // 0..15
    int kq = tid & 15;        // 0..15
    int y  = t*16 + yl;
    size_t rowbase = ((size_t)bc * HH + y) * WW;

    #pragma unroll
    for (int g = 0; g < 4; g++) {
        int k = g*16 + kq;
        int cl = max(k - 1, 0);
        int cr = min(k + 1, 63);
        float al = Ay[yl][cl], am = Ay[yl][k], ar = Ay[yl][cr];
        float bl = By[yl][cl], bm = By[yl][k], br = By[yl][cr];

        float w0 = (k == 0) ? 0.0f : 0.625f;
        float w1 = (k == 0) ? 0.0f : 0.875f;
        float a0 = al + w0 * (am - al);
        float a1 = al + w1 * (am - al);
        float a2 = am + 0.125f * (ar - am);
        float a3 = am + 0.375f * (ar - am);
        float b0 = bl + w0 * (bm - bl);
        float b1 = bl + w1 * (bm - bl);
        float b2 = bm + 0.125f * (br - bm);
        float b3 = bm + 0.375f * (br - bm);

        size_t o4 = rowbase + 4*k;
        float4 e = *(const float4*)(E + o4);
        float4 d = *(const float4*)(D + o4);
        float4 o;
        o.x = d.x + a0 * e.x + b0;
        o.y = d.y + a1 * e.y + b1;
        o.z = d.z + a2 * e.z + b2;
        o.w = d.w + a3 * e.w + b3;
        *(float4*)(out + o4) = o;
    }
}

extern "C" void kernel_launch(void* const* d_in, const int* in_sizes, int n_in,
                              void* d_out, int out_size) {
    const float* F_enc = (const float*)d_in[0];
    const float* F_dec = (const float*)d_in[1];
    const float* w_rg  = (const float*)d_in[2];
    const float* w_rt  = (const float*)d_in[3];
    const float* w_ua  = (const float*)d_in[4];
    const float* w_ub  = (const float*)d_in[5];
    const float* eps   = (const float*)d_in[6];
    float* out = (float*)d_out;

    // K12: fused downsample + projection (c-half partials)
    k_downproj<<<dim3(BB, 32, 4), 256>>>(F_enc, F_dec, w_rg, w_rt);

    // K3: box stats + a,b (sums the two c-half partials on load)
    k_guided<<<BB*RR, 256>>>(eps);

    // K4: expand a,b to C channels at low res
    k_expand<<<dim3(BB, 16, 32), 128>>>(w_ua, w_ub);

    // K5: fused upsample + combine (SMEM-staged coefficients)
    k_final<<<dim3(BB*CC, HH/16), 256>>>(F_enc, F_dec, out);
}

// round 11
// speedup vs baseline: 1.2659x; 1.2659x over previous
#include <cuda_runtime.h>
#include <cuda_bf16.h>

// Problem constants
#define BB 4
#define CC 256
#define HH 256
#define WW 256
#define RR 64
#define HL 64
#define WL 64
#define PL (HL*WL)          // 4096 low-res pixels

typedef unsigned long long u64;

// Scratch (no cudaMalloc allowed -> __device__ globals)
// Partial projections: [which][chalf][b*RR*PL]
__device__ float g_part[2][2][BB*RR*PL];   // 16 MB
__device__ float g_a  [BB*RR*PL];          // 4 MB
__device__ float g_b  [BB*RR*PL];          // 4 MB
__device__ float g_Ai [BB*CC*PL];          // 16 MB  a expanded to C channels (low res)
__device__ float g_Bi [BB*CC*PL];          // 16 MB  b expanded to C channels (low res)

// ---------- packed f32x2 helpers ----------
__device__ __forceinline__ u64 pk2(float lo, float hi) {
    u64 r;
    asm("mov.b64 %0, {%1, %2};" : "=l"(r) : "f"(lo), "f"(hi));
    return r;
}
__device__ __forceinline__ void fma2(u64& acc, u64 a, u64 b) {
    asm("fma.rn.f32x2 %0, %1, %2, %0;" : "+l"(acc) : "l"(a), "l"(b));
}
__device__ __forceinline__ float unpk_sum(u64 v) {
    float lo, hi;
    asm("mov.b64 {%0, %1}, %2;" : "=f"(lo), "=f"(hi) : "l"(v));
    return lo + hi;
}

// ---------- K12: fused 4x downsample + 1x1 projection (R6 measured-best) ----------
// Downsample (align_corners=False, 256->64): lr(i,j) = 0.25 * sum of full-res
// rows {4i+1,4i+2} x cols {4j+1,4j+2}. Then out[b,r,p] = sum_c w[r,c]*lr[b,c,p].
// Block = (b, rp: 2 low-res rows = 128 px, z: bit0 = c-half, bit1 = which).
// NOTE: (256,2) is load-bearing — tighter minctasm caps regs below the 64-reg
// accumulator file and spills (measured +65us).
__global__ __launch_bounds__(256, 2) void k_downproj(const float* __restrict__ E,
                                                     const float* __restrict__ D,
                                                     const float* __restrict__ wg,
                                                     const float* __restrict__ wt) {
    __shared__ u64   ws[64 * 64];      // [cpair][r] duplicated-pair weights, 32 KB
    __shared__ float sds[8 * 256];     // [k][px*2+parity], 8 KB

    int b  = blockIdx.x;               // 0..3
    int rp = blockIdx.y;               // 0..31
    int ch    = blockIdx.z & 1;        // c-half
    int which = blockIdx.z >> 1;       // 0: E/w_rg, 1: D/w_rt
    int tid = threadIdx.x;

    const float* X = which ? D : E;
    const float* w = which ? wt : wg;

    // ws[cp*64 + r] = (w[r][c], w[r][c+1]), c = ch*128 + 2*cp
    for (int i = tid; i < 64 * 64; i += 256) {
        int cp = i >> 6, r = i & 63;
        int c = ch * 128 + cp * 2;
        ws[i] = pk2(w[r * CC + c], w[r * CC + c + 1]);
    }
    __syncthreads();

    int px = tid & 127;                // phase-A pixel
    int c_local = tid >> 7;            // c parity within pair
    int j  = px & 63;
    int il = px >> 6;
    int i_lr = rp * 2 + il;

    int warp = tid >> 5, lane = tid & 31;
    int rbase = (warp >> 2) * 32;
    int mypx  = (warp & 3) * 32 + lane;   // 0..127

    u64 acc[32];
    #pragma unroll
    for (int r = 0; r < 32; r++) acc[r] = 0ull;

    const float4* X4 = (const float4*)X;
    size_t f4row = ((size_t)(b * CC) * HH + (4 * i_lr + 1)) * (WW / 4) + j;
    const size_t cstride = (size_t)HH * (WW / 4);   // f4 elems per channel

    for (int chunk = 0; chunk < 8; chunk++) {
        // ---- phase A: downsample 16 channels for 128 px ----
        #pragma unroll
        for (int k = 0; k < 8; k++) {
            int c = ch * 128 + chunk * 16 + k * 2 + c_local;
            size_t f0 = f4row + (size_t)c * cstride;
            float4 e0 = X4[f0];
            float4 e1 = X4[f0 + WW / 4];
            sds[k * 256 + px * 2 + c_local] =
                0.25f * (e0.y + e0.z + e1.y + e1.z);
        }
        __syncthreads();

        // ---- phase B: 8 c-pairs of FMA ----
        #pragma unroll
        for (int k = 0; k < 8; k++) {
            u64 dsp = *(const u64*)(sds + k * 256 + mypx * 2);
            const u64* wptr = ws + (chunk * 8 + k) * 64 + rbase;
            #pragma unroll
            for (int rr = 0; rr < 32; rr += 2) {
                ulonglong2 wv = *(const ulonglong2*)(wptr + rr);
                fma2(acc[rr],     dsp, wv.x);
                fma2(acc[rr + 1], dsp, wv.y);
            }
        }
        __syncthreads();
    }

    float* outp = g_part[which][ch] + ((size_t)b * RR + rbase) * PL + rp * 128 + mypx;
    #pragma unroll
    for (int r = 0; r < 32; r++)
        outp[(size_t)r * PL] = unpk_sum(acc[r]);
}

// ---------- K3: 3x3 zero-padded box stats + guided-filter coefficients ----------
// Staging loads vectorized to float4 (4 coalesced streams -> 16 LDG.128/thread).
#define PITCH 66
__global__ __launch_bounds__(256) void k_guided(const float* __restrict__ epsPtr) {
    __shared__ float sg[PITCH*PITCH];
    __shared__ float st[PITCH*PITCH];
    int br = blockIdx.x;                       // b*RR + r, 256 blocks
    int tid = threadIdx.x;
    const float4* g0 = (const float4*)(g_part[0][0] + (size_t)br * PL);
    const float4* g1 = (const float4*)(g_part[0][1] + (size_t)br * PL);
    const float4* t0 = (const float4*)(g_part[1][0] + (size_t)br * PL);
    const float4* t1 = (const float4*)(g_part[1][1] + (size_t)br * PL);
    for (int i = tid; i < PITCH*PITCH; i += 256) { sg[i] = 0.0f; st[i] = 0.0f; }
    __syncthreads();
    for (int q = tid; q < PL/4; q += 256) {
        int p = q * 4;
        int i = p >> 6, j = p & 63;          // j is a multiple of 4, j <= 60
        float4 ga = g0[q], gb = g1[q], ta = t0[q], tb = t1[q];
        float* sgp = &sg[(i+1)*PITCH + (j+1)];
        float* stp = &st[(i+1)*PITCH + (j+1)];
        sgp[0] = ga.x + gb.x; sgp[1] = ga.y + gb.y;
        sgp[2] = ga.z + gb.z; sgp[3] = ga.w + gb.w;
        stp[0] = ta.x + tb.x; stp[1] = ta.y + tb.y;
        stp[2] = ta.z + tb.z; stp[3] = ta.w + tb.w;
    }
    __syncthreads();
    float eps = *epsPtr;
    const float inv9 = 1.0f / 9.0f;
    for (int p = tid; p < PL; p += 256) {
        int i = p >> 6, j = p & 63;
        int c = (i+1)*PITCH + (j+1);
        float sgs = 0.f, sts = 0.f, sggs = 0.f, sgts = 0.f;
        #pragma unroll
        for (int di = -1; di <= 1; di++) {
            #pragma unroll
            for (int dj = -1; dj <= 1; dj++) {
                float g = sg[c + di*PITCH + dj];
                float t = st[c + di*PITCH + dj];
                sgs += g; sts += t; sggs += g*g; sgts += g*t;
            }
        }
        float mg  = sgs * inv9;
        float mt  = sts * inv9;
        float var = sggs * inv9 - mg * mg;
        float cov = sgts * inv9 - mg * mt;
        float a   = cov / (var + eps);
        float bb  = mt - a * mg;
        g_a[(size_t)br * PL + p] = a;
        g_b[(size_t)br * PL + p] = bb;
    }
}

// ---------- K4: expand: out[b,o,p] = sum_r w[o,r] * in[b,r,p]  (w: [C, R]) ----------
// Register-tiled (measured-best variant): 16 o-outputs x 2 pixels/thread.
// blockIdx.z (32): bits[0:4) = o-group (16), bit4 = which tensor.
__global__ __launch_bounds__(128, 5) void k_expand(const float* __restrict__ wa,
                                                   const float* __restrict__ wb) {
    __shared__ float ws[16 * RR];
    int which = blockIdx.z >> 4;
    int og    = blockIdx.z & 15;
    const float* in = which ? g_b  : g_a;
    float* out      = which ? g_Bi : g_Ai;
    const float* w  = which ? wb   : wa;
    int b  = blockIdx.x;          // 0..3
    int pt = blockIdx.y;          // 0..15
    int tid = threadIdx.x;

    const float4* wsrc = (const float4*)(w + og * 16 * RR);
    #pragma unroll
    for (int i = tid; i < 16 * RR / 4; i += 128) ((float4*)ws)[i] = wsrc[i];
    __syncthreads();

    int p0 = pt * 256 + tid;
    const float* inb = in + (size_t)b * RR * PL + p0;

    u64 acc0[16], acc1[16];
    #pragma unroll
    for (int o = 0; o < 16; o++) { acc0[o] = 0ull; acc1[o] = 0ull; }

    #pragma unroll 4
    for (int r = 0; r < RR; r += 4) {
        const float* ip = inb + (size_t)r * PL;
        float a0 = ip[0],      a1 = ip[PL],      a2 = ip[2*PL],      a3 = ip[3*PL];
        float b0 = ip[128],    b1 = ip[PL+128],  b2 = ip[2*PL+128],  b3 = ip[3*PL+128];
        u64 ea0 = pk2(a0, a1), ea1 = pk2(a2, a3);
        u64 eb0 = pk2(b0, b1), eb1 = pk2(b2, b3);
        #pragma unroll
        for (int o = 0; o < 16; o++) {
            const ulonglong2 wv = *(const ulonglong2*)(ws + o * RR + r);
            fma2(acc0[o], ea0, wv.x);
            fma2(acc0[o], ea1, wv.y);
            fma2(acc1[o], eb0, wv.x);
            fma2(acc1[o], eb1, wv.y);
        }
    }
    float* outp = out + ((size_t)b * CC + og * 16) * PL + p0;
    #pragma unroll
    for (int o = 0; o < 16; o++) {
        outp[(size_t)o * PL]       = unpk_sum(acc0[o]);
        outp[(size_t)o * PL + 128] = unpk_sum(acc1[o]);
    }
}

// ---------- K5: fused 4x bilinear upsample + output combine (SMEM-staged) ----------
__global__ __launch_bounds__(256) void k_final(const float* __restrict__ E,
                                               const float* __restrict__ D,
                                               float* __restrict__ out) {
    __shared__ float rawA[6][64], rawB[6][64];
    __shared__ float Ay[16][64], By[16][64];
    int bc = blockIdx.x;      // 0..1023
    int t  = blockIdx.y;      // 0..15 (y tiles of 16)
    int tid = threadIdx.x;
    int base = 4*t - 1;

    const float* Ab = g_Ai + (size_t)bc * PL;
    const float* Bb = g_Bi + (size_t)bc * PL;
    for (int i = tid; i < 6*64; i += 256) {
        int s = i >> 6, c = i & 63;
        int row = min(max(base + s, 0), 63);
        rawA[s][c] = Ab[row*64 + c];
        rawB[s][c] = Bb[row*64 + c];
    }
    __syncthreads();

    for (int i = tid; i < 16*64; i += 256) {
        int yl = i >> 6, c = i & 63;
        int y = t*16 + yl;
        float sy = fmaxf((y + 0.5f) * 0.25f - 0.5f, 0.0f);
        int y0 = (int)sy; if (y0 > 63) y0 = 63;
        int y1 = min(y0 + 1, 63);
        float wy = sy - (float)y0;
        int s0 = y0 - base, s1 = y1 - base;
        float a0 = rawA[s0][c], a1 = rawA[s1][c];
        float b0 = rawB[s0][c], b1 = rawB[s1][c];
        Ay[yl][c] = a0 + wy * (a1 - a0);
        By[yl][c] = b0 + wy * (b1 - b0);
    }
    __syncthreads();

    int yl = tid >> 4;        // 0..15
    int kq = tid & 15;        // 0..15
    int y  = t*16 + yl;
    size_t rowbase = ((size_t)bc * HH + y) * WW;

    #pragma unroll
    for (int g = 0; g < 4; g++) {
        int k = g*16 + kq;
        int cl = max(k - 1, 0);
        int cr = min(k + 1, 63);
        float al = Ay[yl][cl], am = Ay[yl][k], ar = Ay[yl][cr];
        float bl = By[yl][cl], bm = By[yl][k], br = By[yl][cr];

        float w0 = (k == 0) ? 0.0f : 0.625f;
        float w1 = (k == 0) ? 0.0f : 0.875f;
        float a0 = al + w0 * (am - al);
        float a1 = al + w1 * (am - al);
        float a2 = am + 0.125f * (ar - am);
        float a3 = am + 0.375f * (ar - am);
        float b0 = bl + w0 * (bm - bl);
        float b1 = bl + w1 * (bm - bl);
        float b2 = bm + 0.125f * (br - bm);
        float b3 = bm + 0.375f * (br - bm);

        size_t o4 = rowbase + 4*k;
        float4 e = *(const float4*)(E + o4);
        float4 d = *(const float4*)(D + o4);
        float4 o;
        o.x = d.x + a0 * e.x + b0;
        o.y = d.y + a1 * e.y + b1;
        o.z = d.z + a2 * e.z + b2;
        o.w = d.w + a3 * e.w + b3;
        *(float4*)(out + o4) = o;
    }
}

extern "C" void kernel_launch(void* const* d_in, const int* in_sizes, int n_in,
                              void* d_out, int out_size) {
    const float* F_enc = (const float*)d_in[0];
    const float* F_dec = (const float*)d_in[1];
    const float* w_rg  = (const float*)d_in[2];
    const float* w_rt  = (const float*)d_in[3];
    const float* w_ua  = (const float*)d_in[4];
    const float* w_ub  = (const float*)d_in[5];
    const float* eps   = (const float*)d_in[6];
    float* out = (float*)d_out;

    // K12: fused downsample + projection (c-half partials)
    k_downproj<<<dim3(BB, 32, 4), 256>>>(F_enc, F_dec, w_rg, w_rt);

    // K3: box stats + a,b (sums the two c-half partials on load)
    k_guided<<<BB*RR, 256>>>(eps);

    // K4: expand a,b to C channels at low res
    k_expand<<<dim3(BB, 16, 32), 128>>>(w_ua, w_ub);

    // K5: fused upsample + combine (SMEM-staged coefficients)
    k_final<<<dim3(BB*CC, HH/16), 256>>>(F_enc, F_dec, out);
}